// round 1
// baseline (speedup 1.0000x reference)
#include <cuda_runtime.h>
#include <cstdint>

#define N_C   100000
#define N_PC  10000
#define NE    1000000
#define D     128
#define NL    3
#define KCOMB 384
#define LN_EPS 1e-5f

// ---------------- device scratch (static, no allocation) ----------------
static __device__ float g_h[N_C * D];
static __device__ float g_pc[N_PC * D];
static __device__ float g_mean0[N_C * D];
static __device__ float g_mean1[N_C * D];
static __device__ int   g_deg[2][N_C];
static __device__ int   g_off[2][N_C + 1];
static __device__ int   g_cur[2][N_C];
static __device__ int   g_esrc[2][NE];
static __device__ float g_wcomb[NL][KCOMB * D];   // [Ws0+Ws1 ; Wn0 ; Wn1]
static __device__ float g_bcomb[NL][D];           // b0+b1

// ---------------- weight prep: combined K=384 weight per layer ----------
__global__ void prep_weights(const float* __restrict__ Wself,
                             const float* __restrict__ Wneigh,
                             const float* __restrict__ bneigh) {
    int idx = blockIdx.x * blockDim.x + threadIdx.x;
    int total = NL * KCOMB * D;
    if (idx < total) {
        int l = idx / (KCOMB * D);
        int rem = idx - l * (KCOMB * D);
        int k = rem / D;
        int n = rem - k * D;
        float v;
        if (k < D) {
            v = Wself[((l * 2 + 0) * D + k) * D + n] +
                Wself[((l * 2 + 1) * D + k) * D + n];
        } else if (k < 2 * D) {
            v = Wneigh[((l * 2 + 0) * D + (k - D)) * D + n];
        } else {
            v = Wneigh[((l * 2 + 1) * D + (k - 2 * D)) * D + n];
        }
        g_wcomb[l][rem] = v;
    }
    if (idx < NL * D) {
        int l = idx / D, n = idx - l * D;
        g_bcomb[l][n] = bneigh[(l * 2 + 0) * D + n] + bneigh[(l * 2 + 1) * D + n];
    }
}

// ---------------- CSR build --------------------------------------------
__global__ void zero_deg() {
    int idx = blockIdx.x * blockDim.x + threadIdx.x;
    if (idx < 2 * N_C) (&g_deg[0][0])[idx] = 0;
}

__global__ void hist_kernel(const int* __restrict__ dst0,
                            const int* __restrict__ dst1) {
    int idx = blockIdx.x * blockDim.x + threadIdx.x;
    if (idx < NE) {
        atomicAdd(&g_deg[0][dst0[idx]], 1);
    } else if (idx < 2 * NE) {
        atomicAdd(&g_deg[1][dst1[idx - NE]], 1);
    }
}

__global__ void scan_kernel() {     // grid = 2 blocks (one per relation)
    int r = blockIdx.x;
    __shared__ int sh[1024];
    __shared__ int s_carry;
    int tid = threadIdx.x;
    if (tid == 0) s_carry = 0;
    __syncthreads();
    int nch = (N_C + 1023) / 1024;
    for (int c = 0; c < nch; c++) {
        int i = c * 1024 + tid;
        int v = (i < N_C) ? g_deg[r][i] : 0;
        sh[tid] = v;
        __syncthreads();
        int incl = v;
        for (int o = 1; o < 1024; o <<= 1) {
            int tval = (tid >= o) ? sh[tid - o] : 0;
            __syncthreads();
            incl += tval;
            sh[tid] = incl;
            __syncthreads();
        }
        int base = s_carry;
        if (i < N_C) {
            int ex = base + incl - v;
            g_off[r][i] = ex;
            g_cur[r][i] = ex;
        }
        __syncthreads();
        if (tid == 1023) s_carry = base + incl;
        __syncthreads();
    }
    if (tid == 0) g_off[r][N_C] = s_carry;
}

__global__ void scatter_kernel(const int* __restrict__ src0,
                               const int* __restrict__ dst0,
                               const int* __restrict__ src1,
                               const int* __restrict__ dst1) {
    int idx = blockIdx.x * blockDim.x + threadIdx.x;
    if (idx < NE) {
        int d = dst0[idx];
        int p = atomicAdd(&g_cur[0][d], 1);
        g_esrc[0][p] = src0[idx];
    } else if (idx < 2 * NE) {
        int e = idx - NE;
        int d = dst1[e];
        int p = atomicAdd(&g_cur[1][d], 1);
        g_esrc[1][p] = src1[e];
    }
}

// ---------------- mean aggregation: warp per destination row -----------
__global__ void agg_kernel(const float* __restrict__ h, int rel) {
    int gw = (blockIdx.x * blockDim.x + threadIdx.x) >> 5;
    int lane = threadIdx.x & 31;
    if (gw >= N_C) return;
    float* __restrict__ out = rel == 0 ? g_mean0 : g_mean1;
    const int* __restrict__ esrc = g_esrc[rel];
    int s = g_off[rel][gw];
    int e = g_off[rel][gw + 1];
    float4 a0 = make_float4(0.f, 0.f, 0.f, 0.f);
    float4 a1 = make_float4(0.f, 0.f, 0.f, 0.f);
    int j = s;
    for (; j + 1 < e; j += 2) {
        int s0 = esrc[j], s1 = esrc[j + 1];
        float4 v0 = ((const float4*)(h + (size_t)s0 * D))[lane];
        float4 v1 = ((const float4*)(h + (size_t)s1 * D))[lane];
        a0.x += v0.x; a0.y += v0.y; a0.z += v0.z; a0.w += v0.w;
        a1.x += v1.x; a1.y += v1.y; a1.z += v1.z; a1.w += v1.w;
    }
    if (j < e) {
        int s0 = esrc[j];
        float4 v0 = ((const float4*)(h + (size_t)s0 * D))[lane];
        a0.x += v0.x; a0.y += v0.y; a0.z += v0.z; a0.w += v0.w;
    }
    float inv = (e > s) ? 1.f / (float)(e - s) : 0.f;
    float4 m;
    m.x = (a0.x + a1.x) * inv;
    m.y = (a0.y + a1.y) * inv;
    m.z = (a0.z + a1.z) * inv;
    m.w = (a0.w + a1.w) * inv;
    ((float4*)(out + (size_t)gw * D))[lane] = m;
}

// ---------------- fused GEMM + bias + LayerNorm + ReLU -----------------
// C[M,128] = [A0|A1|A2][M,K] @ W[K,128]; BM=64, BN=128, BK=16, 256 threads.
// Warp w owns rows bm + w*8 .. +7; lane owns cols lane*4 .. +3 -> row LN via shfl.
__global__ void gemm_ln_kernel(const float* __restrict__ A0,
                               const float* __restrict__ A1,
                               const float* __restrict__ A2,
                               const float* __restrict__ W,
                               const float* __restrict__ bias,
                               const float* __restrict__ gamma,
                               const float* __restrict__ beta,
                               float* __restrict__ out,
                               int M, int K, int relu) {
    __shared__ float As[16 * 68];   // transposed, padded
    __shared__ float Bs[16 * 128];
    int t = threadIdx.x;
    int w = t >> 5, lane = t & 31;
    int bm = blockIdx.x * 64;

    float acc[8][4];
#pragma unroll
    for (int r = 0; r < 8; r++)
#pragma unroll
        for (int c = 0; c < 4; c++) acc[r][c] = 0.f;

    int arow = t >> 2;          // 0..63
    int kq = t & 3;             // 0..3 (k-quad within chunk)
    int grow = bm + arow;

    for (int kt = 0; kt < K; kt += 16) {
        // --- load A tile (transposed into smem) ---
        int kg = kt + kq * 4;
        const float* Aseg = (kg < 128) ? A0 : ((kg < 256) ? A1 : A2);
        float4 av = make_float4(0.f, 0.f, 0.f, 0.f);
        if (grow < M) av = *(const float4*)(Aseg + (size_t)grow * D + (kg & 127));
        As[(kq * 4 + 0) * 68 + arow] = av.x;
        As[(kq * 4 + 1) * 68 + arow] = av.y;
        As[(kq * 4 + 2) * 68 + arow] = av.z;
        As[(kq * 4 + 3) * 68 + arow] = av.w;
        // --- load B tile ---
#pragma unroll
        for (int j = 0; j < 2; j++) {
            int fi = t + j * 256;
            int kl = fi >> 5;
            int n4 = fi & 31;
            *(float4*)&Bs[kl * 128 + n4 * 4] =
                *(const float4*)(W + (size_t)(kt + kl) * D + n4 * 4);
        }
        __syncthreads();
#pragma unroll
        for (int k = 0; k < 16; k++) {
            float4 a0 = *(float4*)&As[k * 68 + w * 8];
            float4 a1 = *(float4*)&As[k * 68 + w * 8 + 4];
            float4 b = *(float4*)&Bs[k * 128 + lane * 4];
            float ar[8] = {a0.x, a0.y, a0.z, a0.w, a1.x, a1.y, a1.z, a1.w};
            float br[4] = {b.x, b.y, b.z, b.w};
#pragma unroll
            for (int r = 0; r < 8; r++)
#pragma unroll
                for (int c = 0; c < 4; c++)
                    acc[r][c] = fmaf(ar[r], br[c], acc[r][c]);
        }
        __syncthreads();
    }

    // --- epilogue: bias + LayerNorm(+ReLU), warp-shuffle row reduction ---
    float4 bi = *(const float4*)(bias + lane * 4);
    float4 ga = *(const float4*)(gamma + lane * 4);
    float4 be = *(const float4*)(beta + lane * 4);
#pragma unroll
    for (int r = 0; r < 8; r++) {
        int row = bm + w * 8 + r;
        float c0 = acc[r][0] + bi.x;
        float c1 = acc[r][1] + bi.y;
        float c2 = acc[r][2] + bi.z;
        float c3 = acc[r][3] + bi.w;
        float s = c0 + c1 + c2 + c3;
        float q = c0 * c0 + c1 * c1 + c2 * c2 + c3 * c3;
#pragma unroll
        for (int o = 16; o > 0; o >>= 1) {
            s += __shfl_xor_sync(0xffffffffu, s, o);
            q += __shfl_xor_sync(0xffffffffu, q, o);
        }
        float m = s * (1.f / 128.f);
        float var = q * (1.f / 128.f) - m * m;
        float rs = rsqrtf(var + LN_EPS);
        float o0 = (c0 - m) * rs * ga.x + be.x;
        float o1 = (c1 - m) * rs * ga.y + be.y;
        float o2 = (c2 - m) * rs * ga.z + be.z;
        float o3 = (c3 - m) * rs * ga.w + be.w;
        if (relu) {
            o0 = fmaxf(o0, 0.f); o1 = fmaxf(o1, 0.f);
            o2 = fmaxf(o2, 0.f); o3 = fmaxf(o3, 0.f);
        }
        if (row < M)
            *(float4*)(out + (size_t)row * D + lane * 4) = make_float4(o0, o1, o2, o3);
    }
}

// ---------------- launch ------------------------------------------------
extern "C" void kernel_launch(void* const* d_in, const int* in_sizes, int n_in,
                              void* d_out, int out_size) {
    const float* x_c   = (const float*)d_in[0];
    const float* x_pc  = (const float*)d_in[1];
    const int*   src0  = (const int*)d_in[2];
    const int*   dst0  = (const int*)d_in[3];
    const int*   src1  = (const int*)d_in[4];
    const int*   dst1  = (const int*)d_in[5];
    const float* Wself = (const float*)d_in[6];
    const float* Wneigh= (const float*)d_in[7];
    const float* bneigh= (const float*)d_in[8];
    const float* linW  = (const float*)d_in[9];
    const float* linb  = (const float*)d_in[10];
    const float* gamma = (const float*)d_in[11];
    const float* beta  = (const float*)d_in[12];
    float* out = (float*)d_out;

    float *p_h, *p_pc, *p_m0, *p_m1, *p_wc, *p_bc;
    cudaGetSymbolAddress((void**)&p_h,  g_h);
    cudaGetSymbolAddress((void**)&p_pc, g_pc);
    cudaGetSymbolAddress((void**)&p_m0, g_mean0);
    cudaGetSymbolAddress((void**)&p_m1, g_mean1);
    cudaGetSymbolAddress((void**)&p_wc, g_wcomb);
    cudaGetSymbolAddress((void**)&p_bc, g_bcomb);

    prep_weights<<<(NL * KCOMB * D + 255) / 256, 256>>>(Wself, Wneigh, bneigh);
    zero_deg<<<(2 * N_C + 255) / 256, 256>>>();
    hist_kernel<<<(2 * NE + 255) / 256, 256>>>(dst0, dst1);
    scan_kernel<<<2, 1024>>>();
    scatter_kernel<<<(2 * NE + 255) / 256, 256>>>(src0, dst0, src1, dst1);

    const float* hin = x_c;
    const float* pcin = x_pc;
    for (int l = 0; l < NL; l++) {
        agg_kernel<<<(N_C + 7) / 8, 256>>>(hin, 0);
        agg_kernel<<<(N_C + 7) / 8, 256>>>(hin, 1);
        float* hout = (l == NL - 1) ? out + (size_t)N_PC * D : p_h;
        gemm_ln_kernel<<<(N_C + 63) / 64, 256>>>(
            hin, p_m0, p_m1,
            p_wc + (size_t)l * KCOMB * D, p_bc + (size_t)l * D,
            gamma + (size_t)l * D, beta + (size_t)l * D,
            hout, N_C, KCOMB, (l < NL - 1) ? 1 : 0);
        float* pcout = (l == NL - 1) ? out : p_pc;
        gemm_ln_kernel<<<(N_PC + 63) / 64, 256>>>(
            pcin, nullptr, nullptr,
            linW + (size_t)l * D * D, linb + (size_t)l * D,
            gamma + (size_t)l * D, beta + (size_t)l * D,
            pcout, N_PC, D, (l < NL - 1) ? 1 : 0);
        hin = hout;
        pcin = pcout;
    }
}

// round 2
// speedup vs baseline: 1.7766x; 1.7766x over previous
#include <cuda_runtime.h>
#include <cstdint>

#define N_C   100000
#define N_PC  10000
#define NE    1000000
#define D     128
#define NL    3
#define KCOMB 384
#define LN_EPS 1e-5f
#define NCHUNK 98          // ceil(N_C/1024)
#define AS_STRIDE 36       // floats per row in A smem (32 + 4 pad -> conflict-free)

// ---------------- device scratch (static, no allocation) ----------------
static __device__ float g_h[N_C * D];
static __device__ float g_pc[N_PC * D];
static __device__ float g_mean0[N_C * D];
static __device__ float g_mean1[N_C * D];
static __device__ int   g_deg[2][N_C];
static __device__ int   g_off[2][N_C + 1];
static __device__ int   g_cur[2][N_C];
static __device__ int   g_esrc[2][NE];
static __device__ int   g_psum[2][NCHUNK + 1];
static __device__ float g_wcomb[NL][KCOMB * D];   // [Ws0+Ws1 ; Wn0 ; Wn1]
static __device__ float g_bcomb[NL][D];           // b0+b1

// ---------------- weight prep: combined K=384 weight per layer ----------
__global__ void prep_weights(const float* __restrict__ Wself,
                             const float* __restrict__ Wneigh,
                             const float* __restrict__ bneigh) {
    int idx = blockIdx.x * blockDim.x + threadIdx.x;
    int total = NL * KCOMB * D;
    if (idx < total) {
        int l = idx / (KCOMB * D);
        int rem = idx - l * (KCOMB * D);
        int k = rem / D;
        int n = rem - k * D;
        float v;
        if (k < D) {
            v = Wself[((l * 2 + 0) * D + k) * D + n] +
                Wself[((l * 2 + 1) * D + k) * D + n];
        } else if (k < 2 * D) {
            v = Wneigh[((l * 2 + 0) * D + (k - D)) * D + n];
        } else {
            v = Wneigh[((l * 2 + 1) * D + (k - 2 * D)) * D + n];
        }
        g_wcomb[l][rem] = v;
    }
    if (idx < NL * D) {
        int l = idx / D, n = idx - l * D;
        g_bcomb[l][n] = bneigh[(l * 2 + 0) * D + n] + bneigh[(l * 2 + 1) * D + n];
    }
}

// ---------------- CSR build --------------------------------------------
__global__ void zero_deg() {
    int idx = blockIdx.x * blockDim.x + threadIdx.x;
    if (idx < 2 * N_C) (&g_deg[0][0])[idx] = 0;
}

__global__ void hist_kernel(const int* __restrict__ dst0,
                            const int* __restrict__ dst1) {
    int idx = blockIdx.x * blockDim.x + threadIdx.x;
    if (idx < NE) {
        atomicAdd(&g_deg[0][dst0[idx]], 1);
    } else if (idx < 2 * NE) {
        atomicAdd(&g_deg[1][dst1[idx - NE]], 1);
    }
}

// 3-phase parallel exclusive scan ---------------------------------------
__global__ void scan_partial() {
    int r = blockIdx.y;
    int i = blockIdx.x * 1024 + threadIdx.x;
    int lane = threadIdx.x & 31, wid = threadIdx.x >> 5;
    int v = (i < N_C) ? g_deg[r][i] : 0;
    int x = v;
#pragma unroll
    for (int o = 1; o < 32; o <<= 1) {
        int y = __shfl_up_sync(0xffffffffu, x, o);
        if (lane >= o) x += y;
    }
    __shared__ int ws[32];
    if (lane == 31) ws[wid] = x;
    __syncthreads();
    if (wid == 0) {
        int y = ws[lane];
#pragma unroll
        for (int o = 1; o < 32; o <<= 1) {
            int z = __shfl_up_sync(0xffffffffu, y, o);
            if (lane >= o) y += z;
        }
        ws[lane] = y;
    }
    __syncthreads();
    int base = wid ? ws[wid - 1] : 0;
    if (i < N_C) g_off[r][i] = base + x - v;
    if (threadIdx.x == 1023) g_psum[r][blockIdx.x] = base + x;
}

__global__ void scan_totals() {
    int r = threadIdx.x;
    if (r < 2) {
        int run = 0;
        for (int c = 0; c < NCHUNK; c++) {
            int t = g_psum[r][c];
            g_psum[r][c] = run;
            run += t;
        }
        g_off[r][N_C] = run;
    }
}

__global__ void add_base() {
    int r = blockIdx.y;
    int i = blockIdx.x * 1024 + threadIdx.x;
    if (i < N_C) {
        int o = g_off[r][i] + g_psum[r][blockIdx.x];
        g_off[r][i] = o;
        g_cur[r][i] = o;
    }
}

__global__ void scatter_kernel(const int* __restrict__ src0,
                               const int* __restrict__ dst0,
                               const int* __restrict__ src1,
                               const int* __restrict__ dst1) {
    int idx = blockIdx.x * blockDim.x + threadIdx.x;
    if (idx < NE) {
        int d = dst0[idx];
        int p = atomicAdd(&g_cur[0][d], 1);
        g_esrc[0][p] = src0[idx];
    } else if (idx < 2 * NE) {
        int e = idx - NE;
        int d = dst1[e];
        int p = atomicAdd(&g_cur[1][d], 1);
        g_esrc[1][p] = src1[e];
    }
}

// ---------------- mean aggregation: warp per destination row -----------
__global__ void agg_kernel(const float* __restrict__ h, int rel) {
    int gw = (blockIdx.x * blockDim.x + threadIdx.x) >> 5;
    int lane = threadIdx.x & 31;
    if (gw >= N_C) return;
    float* __restrict__ out = rel == 0 ? g_mean0 : g_mean1;
    const int* __restrict__ esrc = g_esrc[rel];
    int s = g_off[rel][gw];
    int e = g_off[rel][gw + 1];
    float4 a0 = make_float4(0.f, 0.f, 0.f, 0.f);
    float4 a1 = make_float4(0.f, 0.f, 0.f, 0.f);
    int j = s;
    for (; j + 1 < e; j += 2) {
        int s0 = esrc[j], s1 = esrc[j + 1];
        float4 v0 = ((const float4*)(h + (size_t)s0 * D))[lane];
        float4 v1 = ((const float4*)(h + (size_t)s1 * D))[lane];
        a0.x += v0.x; a0.y += v0.y; a0.z += v0.z; a0.w += v0.w;
        a1.x += v1.x; a1.y += v1.y; a1.z += v1.z; a1.w += v1.w;
    }
    if (j < e) {
        int s0 = esrc[j];
        float4 v0 = ((const float4*)(h + (size_t)s0 * D))[lane];
        a0.x += v0.x; a0.y += v0.y; a0.z += v0.z; a0.w += v0.w;
    }
    float inv = (e > s) ? 1.f / (float)(e - s) : 0.f;
    float4 m;
    m.x = (a0.x + a1.x) * inv;
    m.y = (a0.y + a1.y) * inv;
    m.z = (a0.z + a1.z) * inv;
    m.w = (a0.w + a1.w) * inv;
    ((float4*)(out + (size_t)gw * D))[lane] = m;
}

// ---------------- tf32 mma GEMM + bias + LayerNorm + ReLU --------------
__device__ __forceinline__ uint32_t f2tf(float f) {
    uint32_t u;
    asm("cvt.rna.tf32.f32 %0, %1;" : "=r"(u) : "f"(f));
    return u;
}

__device__ __forceinline__ void mma8(float* c, uint32_t a0, uint32_t a1,
                                     uint32_t a2, uint32_t a3,
                                     uint32_t b0, uint32_t b1) {
    asm volatile(
        "mma.sync.aligned.m16n8k8.row.col.f32.tf32.tf32.f32 "
        "{%0,%1,%2,%3},{%4,%5,%6,%7},{%8,%9},{%0,%1,%2,%3};"
        : "+f"(c[0]), "+f"(c[1]), "+f"(c[2]), "+f"(c[3])
        : "r"(a0), "r"(a1), "r"(a2), "r"(a3), "r"(b0), "r"(b1));
}

// C[M,128] = [A0|A1|A2][M,K] @ W[K,128]; BM=256, BN=128, BK=32.
// 8 warps; warp w owns rows w*32..w*32+31 (2 m16 tiles) x all 128 cols,
// so LayerNorm is a quad-shuffle reduction (lanes 4g..4g+3 share rows).
__global__ __launch_bounds__(256, 1)
void gemm_mma_ln(const float* __restrict__ A0, const float* __restrict__ A1,
                 const float* __restrict__ A2, const float* __restrict__ W,
                 const float* __restrict__ bias, const float* __restrict__ gamma,
                 const float* __restrict__ beta, float* __restrict__ out,
                 int M, int K, int relu) {
    extern __shared__ uint32_t sm[];
    uint32_t* As = sm;                      // [256][AS_STRIDE] (k-major per row)
    uint32_t* Bs = sm + 256 * AS_STRIDE;    // [32][136]
    int t = threadIdx.x, lane = t & 31, w = t >> 5;
    int bm = blockIdx.x * 256;

    float acc[2][16][4];
#pragma unroll
    for (int mt = 0; mt < 2; mt++)
#pragma unroll
        for (int tt = 0; tt < 16; tt++)
#pragma unroll
            for (int c = 0; c < 4; c++) acc[mt][tt][c] = 0.f;

    for (int kt = 0; kt < K; kt += 32) {
        const float* Aseg = (kt < 128) ? A0 : ((kt < 256) ? A1 : A2);
        int kcol = kt & 127;
        // A tile: 256 rows x 32 k; 8 float4/thread; coalesced LDG; STS.128
#pragma unroll
        for (int jj = 0; jj < 8; jj++) {
            int idx = t + jj * 256;
            int row = idx >> 3, k4 = idx & 7;
            float4 av = make_float4(0.f, 0.f, 0.f, 0.f);
            int gr = bm + row;
            if (gr < M) av = *(const float4*)(Aseg + (size_t)gr * D + kcol + k4 * 4);
            *(uint4*)&As[row * AS_STRIDE + k4 * 4] =
                make_uint4(f2tf(av.x), f2tf(av.y), f2tf(av.z), f2tf(av.w));
        }
        // B tile: 32 k x 128 n; 4 float4/thread
#pragma unroll
        for (int i = 0; i < 4; i++) {
            int idx = t + i * 256;
            int kk = idx >> 5, nq = idx & 31;
            float4 bv = *(const float4*)(W + (size_t)(kt + kk) * D + nq * 4);
            *(uint4*)&Bs[kk * 136 + nq * 4] =
                make_uint4(f2tf(bv.x), f2tf(bv.y), f2tf(bv.z), f2tf(bv.w));
        }
        __syncthreads();
#pragma unroll
        for (int ks = 0; ks < 4; ks++) {
            int r0 = w * 32 + (lane >> 2);
            uint32_t a[2][4];
#pragma unroll
            for (int mt = 0; mt < 2; mt++) {
                int rb = r0 + mt * 16;
                a[mt][0] = As[rb * AS_STRIDE + ks * 8 + (lane & 3)];
                a[mt][1] = As[(rb + 8) * AS_STRIDE + ks * 8 + (lane & 3)];
                a[mt][2] = As[rb * AS_STRIDE + ks * 8 + 4 + (lane & 3)];
                a[mt][3] = As[(rb + 8) * AS_STRIDE + ks * 8 + 4 + (lane & 3)];
            }
#pragma unroll
            for (int tt = 0; tt < 16; tt++) {
                uint32_t b0 = Bs[(ks * 8 + (lane & 3)) * 136 + (lane >> 2) + 8 * tt];
                uint32_t b1 = Bs[(ks * 8 + 4 + (lane & 3)) * 136 + (lane >> 2) + 8 * tt];
                mma8(acc[0][tt], a[0][0], a[0][1], a[0][2], a[0][3], b0, b1);
                mma8(acc[1][tt], a[1][0], a[1][1], a[1][2], a[1][3], b0, b1);
            }
        }
        __syncthreads();
    }

    // epilogue: bias + LN (+ReLU); c0/c1 -> row g, c2/c3 -> row g+8
#pragma unroll
    for (int mt = 0; mt < 2; mt++) {
        int rowa = bm + w * 32 + mt * 16 + (lane >> 2);
        int rowb = rowa + 8;
        float s0 = 0.f, q0 = 0.f, s1 = 0.f, q1 = 0.f;
#pragma unroll
        for (int tt = 0; tt < 16; tt++) {
            int col = tt * 8 + (lane & 3) * 2;
            float2 bf = *(const float2*)(bias + col);
            float v0 = acc[mt][tt][0] + bf.x, v1 = acc[mt][tt][1] + bf.y;
            float v2 = acc[mt][tt][2] + bf.x, v3 = acc[mt][tt][3] + bf.y;
            acc[mt][tt][0] = v0; acc[mt][tt][1] = v1;
            acc[mt][tt][2] = v2; acc[mt][tt][3] = v3;
            s0 += v0 + v1; q0 += v0 * v0 + v1 * v1;
            s1 += v2 + v3; q1 += v2 * v2 + v3 * v3;
        }
#pragma unroll
        for (int o = 1; o < 4; o <<= 1) {
            s0 += __shfl_xor_sync(0xffffffffu, s0, o);
            q0 += __shfl_xor_sync(0xffffffffu, q0, o);
            s1 += __shfl_xor_sync(0xffffffffu, s1, o);
            q1 += __shfl_xor_sync(0xffffffffu, q1, o);
        }
        float m0 = s0 * (1.f / 128.f), m1 = s1 * (1.f / 128.f);
        float rs0 = rsqrtf(q0 * (1.f / 128.f) - m0 * m0 + LN_EPS);
        float rs1 = rsqrtf(q1 * (1.f / 128.f) - m1 * m1 + LN_EPS);
#pragma unroll
        for (int tt = 0; tt < 16; tt++) {
            int col = tt * 8 + (lane & 3) * 2;
            float2 g = *(const float2*)(gamma + col);
            float2 be = *(const float2*)(beta + col);
            float o0 = (acc[mt][tt][0] - m0) * rs0 * g.x + be.x;
            float o1 = (acc[mt][tt][1] - m0) * rs0 * g.y + be.y;
            float o2 = (acc[mt][tt][2] - m1) * rs1 * g.x + be.x;
            float o3 = (acc[mt][tt][3] - m1) * rs1 * g.y + be.y;
            if (relu) {
                o0 = fmaxf(o0, 0.f); o1 = fmaxf(o1, 0.f);
                o2 = fmaxf(o2, 0.f); o3 = fmaxf(o3, 0.f);
            }
            if (rowa < M) *(float2*)(out + (size_t)rowa * D + col) = make_float2(o0, o1);
            if (rowb < M) *(float2*)(out + (size_t)rowb * D + col) = make_float2(o2, o3);
        }
    }
}

// ---------------- launch ------------------------------------------------
extern "C" void kernel_launch(void* const* d_in, const int* in_sizes, int n_in,
                              void* d_out, int out_size) {
    const float* x_c   = (const float*)d_in[0];
    const float* x_pc  = (const float*)d_in[1];
    const int*   src0  = (const int*)d_in[2];
    const int*   dst0  = (const int*)d_in[3];
    const int*   src1  = (const int*)d_in[4];
    const int*   dst1  = (const int*)d_in[5];
    const float* Wself = (const float*)d_in[6];
    const float* Wneigh= (const float*)d_in[7];
    const float* bneigh= (const float*)d_in[8];
    const float* linW  = (const float*)d_in[9];
    const float* linb  = (const float*)d_in[10];
    const float* gamma = (const float*)d_in[11];
    const float* beta  = (const float*)d_in[12];
    float* out = (float*)d_out;

    float *p_h, *p_pc, *p_m0, *p_m1, *p_wc, *p_bc;
    cudaGetSymbolAddress((void**)&p_h,  g_h);
    cudaGetSymbolAddress((void**)&p_pc, g_pc);
    cudaGetSymbolAddress((void**)&p_m0, g_mean0);
    cudaGetSymbolAddress((void**)&p_m1, g_mean1);
    cudaGetSymbolAddress((void**)&p_wc, g_wcomb);
    cudaGetSymbolAddress((void**)&p_bc, g_bcomb);

    const int gemm_smem = (256 * AS_STRIDE + 32 * 136) * 4;   // 54272 B
    cudaFuncSetAttribute(gemm_mma_ln,
                         cudaFuncAttributeMaxDynamicSharedMemorySize, gemm_smem);

    prep_weights<<<(NL * KCOMB * D + 255) / 256, 256>>>(Wself, Wneigh, bneigh);
    zero_deg<<<(2 * N_C + 255) / 256, 256>>>();
    hist_kernel<<<(2 * NE + 255) / 256, 256>>>(dst0, dst1);
    scan_partial<<<dim3(NCHUNK, 2), 1024>>>();
    scan_totals<<<1, 32>>>();
    add_base<<<dim3(NCHUNK, 2), 1024>>>();
    scatter_kernel<<<(2 * NE + 255) / 256, 256>>>(src0, dst0, src1, dst1);

    const float* hin = x_c;
    const float* pcin = x_pc;
    for (int l = 0; l < NL; l++) {
        agg_kernel<<<(N_C + 7) / 8, 256>>>(hin, 0);
        agg_kernel<<<(N_C + 7) / 8, 256>>>(hin, 1);
        float* hout = (l == NL - 1) ? out + (size_t)N_PC * D : p_h;
        gemm_mma_ln<<<(N_C + 255) / 256, 256, gemm_smem>>>(
            hin, p_m0, p_m1,
            p_wc + (size_t)l * KCOMB * D, p_bc + (size_t)l * D,
            gamma + (size_t)l * D, beta + (size_t)l * D,
            hout, N_C, KCOMB, (l < NL - 1) ? 1 : 0);
        float* pcout = (l == NL - 1) ? out : p_pc;
        gemm_mma_ln<<<(N_PC + 255) / 256, 256, gemm_smem>>>(
            pcin, pcin, pcin,
            linW + (size_t)l * D * D, linb + (size_t)l * D,
            gamma + (size_t)l * D, beta + (size_t)l * D,
            pcout, N_PC, D, (l < NL - 1) ? 1 : 0);
        hin = hout;
        pcin = pcout;
    }
}